// round 2
// baseline (speedup 1.0000x reference)
#include <cuda_runtime.h>

// x: [B=16, T=4096, D=1024] f32, out: [B, D] = sum over T.
// Two-phase deterministic reduction, HBM-bound (~268 MB traffic, floor ~38us).

#define B_DIM 16
#define T_DIM 4096
#define D_DIM 1024
#define SPLITS 32                 // T-splits per batch
#define ROWS_PER_BLK (T_DIM / SPLITS)   // 128

// Scratch partials: [B, SPLITS, D] f32 = 2 MiB (device global, no alloc).
__device__ float g_partial[B_DIM * SPLITS * D_DIM];

__global__ __launch_bounds__(256, 8)
void sum_phase1(const float* __restrict__ x) {
    const int b = blockIdx.x;          // 0..15
    const int s = blockIdx.y;          // 0..31
    const int tid = threadIdx.x;       // 0..255, handles float4 column tid

    const float4* __restrict__ xp = reinterpret_cast<const float4*>(
        x + (size_t)b * T_DIM * D_DIM + (size_t)s * ROWS_PER_BLK * D_DIM);
    // row stride in float4 units
    const int rstride = D_DIM / 4;     // 256

    float4 acc = make_float4(0.f, 0.f, 0.f, 0.f);

    #pragma unroll 8
    for (int r = 0; r < ROWS_PER_BLK; ++r) {
        float4 v = __ldg(xp + (size_t)r * rstride + tid);
        acc.x += v.x; acc.y += v.y; acc.z += v.z; acc.w += v.w;
    }

    float4* __restrict__ pp = reinterpret_cast<float4*>(
        g_partial + (size_t)(b * SPLITS + s) * D_DIM);
    pp[tid] = acc;
}

__global__ __launch_bounds__(256)
void sum_phase2(float* __restrict__ out) {
    const int idx = blockIdx.x * blockDim.x + threadIdx.x;  // 0..16383
    if (idx >= B_DIM * D_DIM) return;
    const int b = idx / D_DIM;
    const int d = idx % D_DIM;

    float acc = 0.f;
    const float* __restrict__ p = g_partial + (size_t)b * SPLITS * D_DIM + d;
    #pragma unroll
    for (int s = 0; s < SPLITS; ++s)
        acc += p[(size_t)s * D_DIM];
    out[idx] = acc;
}

extern "C" void kernel_launch(void* const* d_in, const int* in_sizes, int n_in,
                              void* d_out, int out_size) {
    const float* x = (const float*)d_in[0];
    float* out = (float*)d_out;

    dim3 g1(B_DIM, SPLITS);
    sum_phase1<<<g1, 256>>>(x);

    int n = B_DIM * D_DIM;
    sum_phase2<<<(n + 255) / 256, 256>>>(out);
}

// round 3
// speedup vs baseline: 1.0041x; 1.0041x over previous
#include <cuda_runtime.h>

// x: [B=16, T=4096, D=1024] f32, out: [B, D] = sum over T.
// Single fused kernel: 32 T-split partial blocks per batch; the last block to
// finish each batch (atomic ticket) performs that batch's final 32-way
// reduction in a fixed order (deterministic) and resets the ticket so the
// kernel is graph-replay safe. Saves the ~5us standalone phase-2 launch.

#define B_DIM 16
#define T_DIM 4096
#define D_DIM 1024
#define SPLITS 32
#define ROWS_PER_BLK (T_DIM / SPLITS)   // 128

// Scratch partials: [B, SPLITS, D] f32 = 2 MiB.
__device__ float g_partial[B_DIM * SPLITS * D_DIM];
// Per-batch completion tickets (zero-init at load; reset by reducer each run).
__device__ int g_count[B_DIM];

__global__ __launch_bounds__(256, 8)
void sum_fused(const float* __restrict__ x, float* __restrict__ out) {
    const int b = blockIdx.x;          // 0..15
    const int s = blockIdx.y;          // 0..31
    const int tid = threadIdx.x;       // 0..255 -> one float4 column

    const float4* __restrict__ xp = reinterpret_cast<const float4*>(
        x + (size_t)b * T_DIM * D_DIM + (size_t)s * ROWS_PER_BLK * D_DIM);
    const int rstride = D_DIM / 4;     // 256 float4 per row

    float4 acc = make_float4(0.f, 0.f, 0.f, 0.f);

    #pragma unroll 8
    for (int r = 0; r < ROWS_PER_BLK; ++r) {
        // Streaming (evict-first) load: read-once data, keep L2 for partials.
        float4 v = __ldcs(xp + (size_t)r * rstride + tid);
        acc.x += v.x; acc.y += v.y; acc.z += v.z; acc.w += v.w;
    }

    float4* __restrict__ pp = reinterpret_cast<float4*>(
        g_partial + (size_t)(b * SPLITS + s) * D_DIM);
    pp[tid] = acc;

    // Make partial visible, then take a ticket for this batch.
    __threadfence();
    __shared__ int s_is_last;
    if (tid == 0) {
        int ticket = atomicAdd(&g_count[b], 1);
        s_is_last = (ticket == SPLITS - 1);
    }
    __syncthreads();

    if (s_is_last) {
        // This block is the last finisher for batch b: reduce the 32 partials
        // in fixed s-order (deterministic result), write output, reset ticket.
        const float4* __restrict__ base = reinterpret_cast<const float4*>(
            g_partial + (size_t)b * SPLITS * D_DIM);
        float4 r = make_float4(0.f, 0.f, 0.f, 0.f);
        #pragma unroll
        for (int ss = 0; ss < SPLITS; ++ss) {
            float4 v = base[(size_t)ss * (D_DIM / 4) + tid];
            r.x += v.x; r.y += v.y; r.z += v.z; r.w += v.w;
        }
        reinterpret_cast<float4*>(out + (size_t)b * D_DIM)[tid] = r;
        if (tid == 0) g_count[b] = 0;   // graph-replay safe
    }
}

extern "C" void kernel_launch(void* const* d_in, const int* in_sizes, int n_in,
                              void* d_out, int out_size) {
    const float* x = (const float*)d_in[0];
    float* out = (float*)d_out;

    dim3 grid(B_DIM, SPLITS);
    sum_fused<<<grid, 256>>>(x, out);
}